// round 5
// baseline (speedup 1.0000x reference)
#include <cuda_runtime.h>

#define NNODE_MAX 100000
#define EDGE_MAX  3200000
#define HH 128
#define FIN 128
#define CC 40
#define LL 3

// ---------------- scratch (no allocations allowed) ----------------
__device__ float g_x[(size_t)NNODE_MAX * HH];
__device__ float g_hin[(size_t)NNODE_MAX * HH];
__device__ float g_m[(size_t)NNODE_MAX * HH];
__device__ float g_agg[(size_t)NNODE_MAX * HH];
__device__ float g_gi[(size_t)NNODE_MAX * 3 * HH];
__device__ float g_gh[(size_t)NNODE_MAX * 3 * HH];
__device__ float g_bnstats[2 * HH];   // [0:128) sum, [128:256) sumsq
__device__ float g_scale[HH];
__device__ float g_shift[HH];
__device__ int   g_ei[(size_t)2 * EDGE_MAX];   // converted int32 src||dst
__device__ int   g_flag[1];                    // 1 => input edge_index is int32

// ---------------- edge_index dtype probe ----------------
// Interpret the buffer as int64 and look at the first 1024 values. If the
// storage is really int32 (JAX x64 disabled), each int64 slot combines two
// random indices: value = lo + hi*2^32 with hi in [0,100000) -> out of range
// almost surely. If true int64, all values are in [0, M).
__global__ void detect_idx_dtype(const long long* __restrict__ ei64, int M,
                                 int* __restrict__ flag)
{
    __shared__ int bad;
    if (threadIdx.x == 0) bad = 0;
    __syncthreads();
    long long v = ei64[threadIdx.x];   // E >= 1024 int64 slots in either layout
    if (v < 0 || v >= (long long)M) bad = 1;
    __syncthreads();
    if (threadIdx.x == 0) *flag = bad;
}

// ---------------- convert edge_index to int32 (handles both dtypes) --------
__global__ void convert_idx(const void* __restrict__ ei, int twoE,
                            const int* __restrict__ flag, int* __restrict__ out)
{
    int i = blockIdx.x * blockDim.x + threadIdx.x;
    if (i >= twoE) return;
    int v;
    if (*flag) v = ((const int*)ei)[i];
    else       v = (int)(((const long long*)ei)[i]);
    out[i] = v;
}

// ---------------- generic 64x64x16 register-tiled SGEMM ----------------
// C[M,Ncols] = A[M,K] @ B + bias
// bTrans==0 : B row-major [K, Ncols]
// bTrans==1 : B stored [Ncols, K] (i.e. C = A @ B^T)
// If A2 != nullptr: A'[r,k] = A[r,k]*ascale[k] + ashift[k] + A2[r,k]  (BN + residual fusion)
__global__ __launch_bounds__(256) void sgemm64(
    const float* __restrict__ A, const float* __restrict__ B,
    const float* __restrict__ bias, float* __restrict__ C,
    int M, int Ncols, int K, int bTrans,
    const float* __restrict__ A2, const float* __restrict__ ascale,
    const float* __restrict__ ashift)
{
    __shared__ float As[16][64];
    __shared__ float Bs[16][64];

    const int tid  = threadIdx.x;
    const int bm   = blockIdx.y * 64;
    const int bn   = blockIdx.x * 64;
    const int trow = (tid >> 4) << 2;   // 0..60
    const int tcol = (tid & 15) << 2;   // 0..60

    const int aRow = tid >> 2;          // 0..63
    const int aCol = (tid & 3) << 2;    // 0,4,8,12
    const int bRow = tid >> 4;          // 0..15
    const int bCol = (tid & 15) << 2;   // 0..60

    float acc[4][4] = {};

    for (int k0 = 0; k0 < K; k0 += 16) {
        // ---- load A tile (64 rows x 16 k), store transposed As[k][m] ----
        float4 av = make_float4(0.f, 0.f, 0.f, 0.f);
        int gr = bm + aRow;
        if (gr < M) {
            av = *reinterpret_cast<const float4*>(A + (size_t)gr * K + k0 + aCol);
            if (A2 != nullptr) {
                float4 a2 = *reinterpret_cast<const float4*>(A2 + (size_t)gr * K + k0 + aCol);
                int kk = k0 + aCol;
                av.x = av.x * ascale[kk + 0] + ashift[kk + 0] + a2.x;
                av.y = av.y * ascale[kk + 1] + ashift[kk + 1] + a2.y;
                av.z = av.z * ascale[kk + 2] + ashift[kk + 2] + a2.z;
                av.w = av.w * ascale[kk + 3] + ashift[kk + 3] + a2.w;
            }
        }
        As[aCol + 0][aRow] = av.x;
        As[aCol + 1][aRow] = av.y;
        As[aCol + 2][aRow] = av.z;
        As[aCol + 3][aRow] = av.w;

        // ---- load B tile (16 k x 64 n) ----
        if (!bTrans) {
            int gn = bn + bCol;
            const float* bp = B + (size_t)(k0 + bRow) * Ncols + gn;
            float4 bv = make_float4(0.f, 0.f, 0.f, 0.f);
            if (gn + 3 < Ncols) {
                bv = *reinterpret_cast<const float4*>(bp);
            } else {
                if (gn + 0 < Ncols) bv.x = bp[0];
                if (gn + 1 < Ncols) bv.y = bp[1];
                if (gn + 2 < Ncols) bv.z = bp[2];
                if (gn + 3 < Ncols) bv.w = bp[3];
            }
            Bs[bRow][bCol + 0] = bv.x;
            Bs[bRow][bCol + 1] = bv.y;
            Bs[bRow][bCol + 2] = bv.z;
            Bs[bRow][bCol + 3] = bv.w;
        } else {
            int nIdx = tid >> 2;           // 0..63
            int kIdx = (tid & 3) << 2;     // 0,4,8,12
            int gn = bn + nIdx;
            float4 bv = make_float4(0.f, 0.f, 0.f, 0.f);
            if (gn < Ncols)
                bv = *reinterpret_cast<const float4*>(B + (size_t)gn * K + k0 + kIdx);
            Bs[kIdx + 0][nIdx] = bv.x;
            Bs[kIdx + 1][nIdx] = bv.y;
            Bs[kIdx + 2][nIdx] = bv.z;
            Bs[kIdx + 3][nIdx] = bv.w;
        }
        __syncthreads();

        // ---- 4x4 micro-tile FMA ----
        #pragma unroll
        for (int k = 0; k < 16; k++) {
            float4 a = *reinterpret_cast<const float4*>(&As[k][trow]);
            float4 b = *reinterpret_cast<const float4*>(&Bs[k][tcol]);
            acc[0][0] += a.x * b.x; acc[0][1] += a.x * b.y; acc[0][2] += a.x * b.z; acc[0][3] += a.x * b.w;
            acc[1][0] += a.y * b.x; acc[1][1] += a.y * b.y; acc[1][2] += a.y * b.z; acc[1][3] += a.y * b.w;
            acc[2][0] += a.z * b.x; acc[2][1] += a.z * b.y; acc[2][2] += a.z * b.z; acc[2][3] += a.z * b.w;
            acc[3][0] += a.w * b.x; acc[3][1] += a.w * b.y; acc[3][2] += a.w * b.z; acc[3][3] += a.w * b.w;
        }
        __syncthreads();
    }

    #pragma unroll
    for (int i = 0; i < 4; i++) {
        int gr = bm + trow + i;
        if (gr >= M) continue;
        #pragma unroll
        for (int j = 0; j < 4; j++) {
            int gn = bn + tcol + j;
            if (gn < Ncols) {
                float v = acc[i][j];
                if (bias != nullptr) v += bias[gn];
                C[(size_t)gr * Ncols + gn] = v;
            }
        }
    }
}

// ---------------- zero fill ----------------
__global__ void zero_kernel(float* __restrict__ p, int n)
{
    int i = blockIdx.x * blockDim.x + threadIdx.x;
    if (i < n) p[i] = 0.f;
}

// ---------------- edge gather + weighted scatter-add ----------------
// One warp per edge: lane l handles floats [4l, 4l+4) of the 128-float row.
__global__ void edge_scatter(const int* __restrict__ srcdst,
                             const float* __restrict__ ew,
                             const float* __restrict__ m,
                             float* __restrict__ agg, int E)
{
    long long gt = (long long)blockIdx.x * blockDim.x + threadIdx.x;
    int e = (int)(gt >> 5);
    if (e >= E) return;
    int lane = threadIdx.x & 31;
    int src = srcdst[e];
    int dst = srcdst[E + e];
    float w = ew[e];
    float4 v = *reinterpret_cast<const float4*>(m + ((size_t)src << 7) + lane * 4);
    float* dp = agg + ((size_t)dst << 7) + lane * 4;
    asm volatile("red.global.add.v4.f32 [%0], {%1, %2, %3, %4};"
                 :: "l"(dp), "f"(v.x * w), "f"(v.y * w), "f"(v.z * w), "f"(v.w * w)
                 : "memory");
}

// ---------------- GRU elementwise update (in-place on x) ----------------
__global__ void gru_update(const float* __restrict__ gi, const float* __restrict__ gh,
                           float* __restrict__ x, int total)
{
    int idx = blockIdx.x * blockDim.x + threadIdx.x;
    if (idx >= total) return;
    int n = idx >> 7;
    int c = idx & 127;
    size_t b = (size_t)n * 384;
    float ir = gi[b + c],        hr = gh[b + c];
    float iz = gi[b + 128 + c],  hz = gh[b + 128 + c];
    float in_ = gi[b + 256 + c], hn = gh[b + 256 + c];
    float r = 1.f / (1.f + expf(-(ir + hr)));
    float z = 1.f / (1.f + expf(-(iz + hz)));
    float nn = tanhf(in_ + r * hn);
    x[idx] = (1.f - z) * nn + z * x[idx];
}

// ---------------- BatchNorm column statistics ----------------
__global__ void bn_stats(const float* __restrict__ x, float* __restrict__ bnSum,
                         float* __restrict__ bnSq, int M)
{
    int c = threadIdx.x;            // 0..127
    int r0 = blockIdx.x * 128;
    float s = 0.f, sq = 0.f;
    #pragma unroll 4
    for (int i = 0; i < 128; i++) {
        int r = r0 + i;
        if (r < M) {
            float v = x[(size_t)r * HH + c];
            s += v;
            sq += v * v;
        }
    }
    atomicAdd(&bnSum[c], s);
    atomicAdd(&bnSq[c], sq);
}

__global__ void bn_final(const float* __restrict__ bnSum, const float* __restrict__ bnSq,
                         const float* __restrict__ gamma, const float* __restrict__ beta,
                         float* __restrict__ scale, float* __restrict__ shift, int M)
{
    int c = threadIdx.x;
    float invN = 1.f / (float)M;
    float mean = bnSum[c] * invN;
    float var = bnSq[c] * invN - mean * mean;
    float sc = gamma[c] * rsqrtf(var + 1e-5f);
    scale[c] = sc;
    shift[c] = beta[c] - mean * sc;
}

// ---------------- launch ----------------
extern "C" void kernel_launch(void* const* d_in, const int* in_sizes, int n_in,
                              void* d_out, int out_size)
{
    const float* h      = (const float*)d_in[0];
    const void*  ei_raw = d_in[1];
    const float* ew     = (const float*)d_in[2];
    const float* emb_W  = (const float*)d_in[3];
    const float* emb_b  = (const float*)d_in[4];
    const float* conv_w = (const float*)d_in[5];
    const float* Wih    = (const float*)d_in[6];
    const float* Whh    = (const float*)d_in[7];
    const float* bih    = (const float*)d_in[8];
    const float* bhh    = (const float*)d_in[9];
    const float* gamma  = (const float*)d_in[10];
    const float* beta   = (const float*)d_in[11];
    const float* mlp_W  = (const float*)d_in[12];
    const float* mlp_b  = (const float*)d_in[13];
    float* out = (float*)d_out;

    const int M = in_sizes[0] / FIN;   // nodes
    const int E = in_sizes[2];         // edges (edge_weight count)

    float *px, *phin, *pm, *pagg, *pgi, *pgh, *pbn, *pscale, *pshift;
    int *pei, *pflag;
    cudaGetSymbolAddress((void**)&px,     g_x);
    cudaGetSymbolAddress((void**)&phin,   g_hin);
    cudaGetSymbolAddress((void**)&pm,     g_m);
    cudaGetSymbolAddress((void**)&pagg,   g_agg);
    cudaGetSymbolAddress((void**)&pgi,    g_gi);
    cudaGetSymbolAddress((void**)&pgh,    g_gh);
    cudaGetSymbolAddress((void**)&pbn,    g_bnstats);
    cudaGetSymbolAddress((void**)&pscale, g_scale);
    cudaGetSymbolAddress((void**)&pshift, g_shift);
    cudaGetSymbolAddress((void**)&pei,    g_ei);
    cudaGetSymbolAddress((void**)&pflag,  g_flag);

    const dim3 blk(256);
    const int total = M * HH;

    // 0. edge_index dtype probe + conversion to int32
    detect_idx_dtype<<<1, 1024>>>((const long long*)ei_raw, M, pflag);
    convert_idx<<<(2 * E + 255) / 256, 256>>>(ei_raw, 2 * E, pflag, pei);

    // 1. x = h @ emb_W + emb_b ; h_in = x
    sgemm64<<<dim3((HH + 63) / 64, (M + 63) / 64), blk>>>(
        h, emb_W, emb_b, px, M, HH, FIN, 0, nullptr, nullptr, nullptr);
    cudaMemcpyAsync(phin, px, (size_t)total * sizeof(float), cudaMemcpyDeviceToDevice);

    // 2. L GatedGraphConv GRU steps
    for (int l = 0; l < LL; l++) {
        sgemm64<<<dim3((HH + 63) / 64, (M + 63) / 64), blk>>>(
            px, conv_w + (size_t)l * HH * HH, nullptr, pm, M, HH, HH, 0,
            nullptr, nullptr, nullptr);
        zero_kernel<<<(total + 255) / 256, 256>>>(pagg, total);
        long long tth = (long long)E * 32;
        edge_scatter<<<(unsigned)((tth + 255) / 256), 256>>>(pei, ew, pm, pagg, E);
        sgemm64<<<dim3((3 * HH + 63) / 64, (M + 63) / 64), blk>>>(
            pagg, Wih, bih, pgi, M, 3 * HH, HH, 1, nullptr, nullptr, nullptr);
        sgemm64<<<dim3((3 * HH + 63) / 64, (M + 63) / 64), blk>>>(
            px, Whh, bhh, pgh, M, 3 * HH, HH, 1, nullptr, nullptr, nullptr);
        gru_update<<<(total + 255) / 256, 256>>>(pgi, pgh, px, total);
    }

    // 3. BatchNorm statistics -> per-feature scale/shift
    zero_kernel<<<1, 256>>>(pbn, 2 * HH);
    bn_stats<<<(M + 127) / 128, 128>>>(px, pbn, pbn + HH, M);
    bn_final<<<1, HH>>>(pbn, pbn + HH, gamma, beta, pscale, pshift, M);

    // 4. out = (BN(x) + h_in) @ mlp_W + mlp_b   (BN + residual fused in A-load)
    sgemm64<<<dim3((CC + 63) / 64, (M + 63) / 64), blk>>>(
        px, mlp_W, mlp_b, out, M, CC, FIN, 0, phin, pscale, pshift);
}

// round 6
// speedup vs baseline: 1.0000x; 1.0000x over previous
#include <cuda_runtime.h>

#define NNODE_MAX 100000
#define EDGE_MAX  3200000
#define HH 128
#define FIN 128
#define CC 40
#define LL 3

// ---------------- scratch (no allocations allowed) ----------------
__device__ float g_x[(size_t)NNODE_MAX * HH];
__device__ float g_hin[(size_t)NNODE_MAX * HH];
__device__ float g_m[(size_t)NNODE_MAX * HH];
__device__ float g_agg[(size_t)NNODE_MAX * HH];
__device__ float g_gi[(size_t)NNODE_MAX * 3 * HH];
__device__ float g_gh[(size_t)NNODE_MAX * 3 * HH];
__device__ float g_bnstats[2 * HH];
__device__ float g_scale[HH];
__device__ float g_shift[HH];
__device__ int   g_ei[(size_t)2 * EDGE_MAX];
__device__ int   g_flag[1];

// ---------------- edge_index dtype probe ----------------
__global__ void detect_idx_dtype(const long long* __restrict__ ei64, int M,
                                 int* __restrict__ flag)
{
    __shared__ int bad;
    if (threadIdx.x == 0) bad = 0;
    __syncthreads();
    long long v = ei64[threadIdx.x];
    if (v < 0 || v >= (long long)M) bad = 1;
    __syncthreads();
    if (threadIdx.x == 0) *flag = bad;
}

__global__ void convert_idx(const void* __restrict__ ei, int twoE,
                            const int* __restrict__ flag, int* __restrict__ out)
{
    int i = blockIdx.x * blockDim.x + threadIdx.x;
    if (i >= twoE) return;
    int v;
    if (*flag) v = ((const int*)ei)[i];
    else       v = (int)(((const long long*)ei)[i]);
    out[i] = v;
}

// ---------------- 128x128x16 register-tiled SGEMM, 8x8 micro-tile ----------
// C[M,Ncols] = A[M,K] @ B + bias
// bTrans==0 : B row-major [K, Ncols];  bTrans==1 : B stored [Ncols, K]
// If A2 != nullptr: A'[r,k] = A[r,k]*ascale[k] + ashift[k] + A2[r,k]
__global__ __launch_bounds__(256, 2) void sgemm128(
    const float* __restrict__ A, const float* __restrict__ B,
    const float* __restrict__ bias, float* __restrict__ C,
    int M, int Ncols, int K, int bTrans,
    const float* __restrict__ A2, const float* __restrict__ ascale,
    const float* __restrict__ ashift)
{
    __shared__ float As[16][132];   // padded: transposed A tile, As[k][m]
    __shared__ float Bs[16][128];   // Bs[k][n]

    const int tid = threadIdx.x;
    const int bm  = blockIdx.y * 128;
    const int bn  = blockIdx.x * 128;
    const int tx  = tid & 15;       // col group
    const int ty  = tid >> 4;       // row group
    const int crow = ty * 8;
    const int ccol = tx * 8;

    // A-tile loader: 128 rows x 16 k = 512 float4; 2 per thread
    const int aRow = tid >> 1;            // 0..127
    const int aK   = (tid & 1) * 8;       // 0 or 8

    float acc[8][8] = {};

    for (int k0 = 0; k0 < K; k0 += 16) {
        // ---- load A tile, store transposed ----
        {
            float4 a0 = make_float4(0.f, 0.f, 0.f, 0.f);
            float4 a1 = make_float4(0.f, 0.f, 0.f, 0.f);
            int gr = bm + aRow;
            if (gr < M) {
                const float* ap = A + (size_t)gr * K + k0 + aK;
                a0 = *reinterpret_cast<const float4*>(ap);
                a1 = *reinterpret_cast<const float4*>(ap + 4);
                if (A2 != nullptr) {
                    const float* a2p = A2 + (size_t)gr * K + k0 + aK;
                    float4 r0 = *reinterpret_cast<const float4*>(a2p);
                    float4 r1 = *reinterpret_cast<const float4*>(a2p + 4);
                    int kk = k0 + aK;
                    a0.x = a0.x * ascale[kk + 0] + ashift[kk + 0] + r0.x;
                    a0.y = a0.y * ascale[kk + 1] + ashift[kk + 1] + r0.y;
                    a0.z = a0.z * ascale[kk + 2] + ashift[kk + 2] + r0.z;
                    a0.w = a0.w * ascale[kk + 3] + ashift[kk + 3] + r0.w;
                    a1.x = a1.x * ascale[kk + 4] + ashift[kk + 4] + r1.x;
                    a1.y = a1.y * ascale[kk + 5] + ashift[kk + 5] + r1.y;
                    a1.z = a1.z * ascale[kk + 6] + ashift[kk + 6] + r1.z;
                    a1.w = a1.w * ascale[kk + 7] + ashift[kk + 7] + r1.w;
                }
            }
            As[aK + 0][aRow] = a0.x;
            As[aK + 1][aRow] = a0.y;
            As[aK + 2][aRow] = a0.z;
            As[aK + 3][aRow] = a0.w;
            As[aK + 4][aRow] = a1.x;
            As[aK + 5][aRow] = a1.y;
            As[aK + 6][aRow] = a1.z;
            As[aK + 7][aRow] = a1.w;
        }

        // ---- load B tile ----
        if (!bTrans) {
            const int bCol = (tid & 31) * 4;     // 0..124
            const int bRow0 = tid >> 5;          // 0..7
            #pragma unroll
            for (int hh = 0; hh < 2; hh++) {
                int row = bRow0 + hh * 8;
                int gn = bn + bCol;
                const float* bp = B + (size_t)(k0 + row) * Ncols + gn;
                float4 bv = make_float4(0.f, 0.f, 0.f, 0.f);
                if (gn + 3 < Ncols) {
                    bv = *reinterpret_cast<const float4*>(bp);
                } else {
                    if (gn + 0 < Ncols) bv.x = bp[0];
                    if (gn + 1 < Ncols) bv.y = bp[1];
                    if (gn + 2 < Ncols) bv.z = bp[2];
                    if (gn + 3 < Ncols) bv.w = bp[3];
                }
                *reinterpret_cast<float4*>(&Bs[row][bCol]) = bv;
            }
        } else {
            const int nI = tid & 127;            // 0..127
            const int kH = (tid >> 7) * 8;       // 0 or 8
            int gn = bn + nI;
            float4 b0 = make_float4(0.f, 0.f, 0.f, 0.f);
            float4 b1 = make_float4(0.f, 0.f, 0.f, 0.f);
            if (gn < Ncols) {
                const float* bp = B + (size_t)gn * K + k0 + kH;
                b0 = *reinterpret_cast<const float4*>(bp);
                b1 = *reinterpret_cast<const float4*>(bp + 4);
            }
            Bs[kH + 0][nI] = b0.x;
            Bs[kH + 1][nI] = b0.y;
            Bs[kH + 2][nI] = b0.z;
            Bs[kH + 3][nI] = b0.w;
            Bs[kH + 4][nI] = b1.x;
            Bs[kH + 5][nI] = b1.y;
            Bs[kH + 6][nI] = b1.z;
            Bs[kH + 7][nI] = b1.w;
        }
        __syncthreads();

        // ---- 8x8 micro-tile FMA over 16 k-steps ----
        #pragma unroll
        for (int k = 0; k < 16; k++) {
            float a[8], b[8];
            *reinterpret_cast<float4*>(&a[0]) = *reinterpret_cast<const float4*>(&As[k][crow]);
            *reinterpret_cast<float4*>(&a[4]) = *reinterpret_cast<const float4*>(&As[k][crow + 4]);
            *reinterpret_cast<float4*>(&b[0]) = *reinterpret_cast<const float4*>(&Bs[k][ccol]);
            *reinterpret_cast<float4*>(&b[4]) = *reinterpret_cast<const float4*>(&Bs[k][ccol + 4]);
            #pragma unroll
            for (int i = 0; i < 8; i++)
                #pragma unroll
                for (int j = 0; j < 8; j++)
                    acc[i][j] += a[i] * b[j];
        }
        __syncthreads();
    }

    // ---- epilogue ----
    #pragma unroll
    for (int i = 0; i < 8; i++) {
        int gr = bm + crow + i;
        if (gr >= M) continue;
        #pragma unroll
        for (int j = 0; j < 8; j++) {
            int gn = bn + ccol + j;
            if (gn < Ncols) {
                float v = acc[i][j];
                if (bias != nullptr) v += bias[gn];
                C[(size_t)gr * Ncols + gn] = v;
            }
        }
    }
}

// ---------------- zero fill ----------------
__global__ void zero_kernel(float* __restrict__ p, int n)
{
    int i = blockIdx.x * blockDim.x + threadIdx.x;
    if (i < n) p[i] = 0.f;
}

// ---------------- edge gather + weighted scatter-add ----------------
__global__ void edge_scatter(const int* __restrict__ srcdst,
                             const float* __restrict__ ew,
                             const float* __restrict__ m,
                             float* __restrict__ agg, int E)
{
    long long gt = (long long)blockIdx.x * blockDim.x + threadIdx.x;
    int e = (int)(gt >> 5);
    if (e >= E) return;
    int lane = threadIdx.x & 31;
    int src = srcdst[e];
    int dst = srcdst[E + e];
    float w = ew[e];
    float4 v = *reinterpret_cast<const float4*>(m + ((size_t)src << 7) + lane * 4);
    float* dp = agg + ((size_t)dst << 7) + lane * 4;
    asm volatile("red.global.add.v4.f32 [%0], {%1, %2, %3, %4};"
                 :: "l"(dp), "f"(v.x * w), "f"(v.y * w), "f"(v.z * w), "f"(v.w * w)
                 : "memory");
}

// ---------------- GRU elementwise update (in-place on x) ----------------
__global__ void gru_update(const float* __restrict__ gi, const float* __restrict__ gh,
                           float* __restrict__ x, int total)
{
    int idx = blockIdx.x * blockDim.x + threadIdx.x;
    if (idx >= total) return;
    int n = idx >> 7;
    int c = idx & 127;
    size_t b = (size_t)n * 384;
    float ir = gi[b + c],        hr = gh[b + c];
    float iz = gi[b + 128 + c],  hz = gh[b + 128 + c];
    float in_ = gi[b + 256 + c], hn = gh[b + 256 + c];
    float r = 1.f / (1.f + expf(-(ir + hr)));
    float z = 1.f / (1.f + expf(-(iz + hz)));
    float nn = tanhf(in_ + r * hn);
    x[idx] = (1.f - z) * nn + z * x[idx];
}

// ---------------- BatchNorm column statistics ----------------
__global__ void bn_stats(const float* __restrict__ x, float* __restrict__ bnSum,
                         float* __restrict__ bnSq, int M)
{
    int c = threadIdx.x;
    int r0 = blockIdx.x * 128;
    float s = 0.f, sq = 0.f;
    #pragma unroll 4
    for (int i = 0; i < 128; i++) {
        int r = r0 + i;
        if (r < M) {
            float v = x[(size_t)r * HH + c];
            s += v;
            sq += v * v;
        }
    }
    atomicAdd(&bnSum[c], s);
    atomicAdd(&bnSq[c], sq);
}

__global__ void bn_final(const float* __restrict__ bnSum, const float* __restrict__ bnSq,
                         const float* __restrict__ gamma, const float* __restrict__ beta,
                         float* __restrict__ scale, float* __restrict__ shift, int M)
{
    int c = threadIdx.x;
    float invN = 1.f / (float)M;
    float mean = bnSum[c] * invN;
    float var = bnSq[c] * invN - mean * mean;
    float sc = gamma[c] * rsqrtf(var + 1e-5f);
    scale[c] = sc;
    shift[c] = beta[c] - mean * sc;
}

// ---------------- launch ----------------
extern "C" void kernel_launch(void* const* d_in, const int* in_sizes, int n_in,
                              void* d_out, int out_size)
{
    const float* h      = (const float*)d_in[0];
    const void*  ei_raw = d_in[1];
    const float* ew     = (const float*)d_in[2];
    const float* emb_W  = (const float*)d_in[3];
    const float* emb_b  = (const float*)d_in[4];
    const float* conv_w = (const float*)d_in[5];
    const float* Wih    = (const float*)d_in[6];
    const float* Whh    = (const float*)d_in[7];
    const float* bih    = (const float*)d_in[8];
    const float* bhh    = (const float*)d_in[9];
    const float* gamma  = (const float*)d_in[10];
    const float* beta   = (const float*)d_in[11];
    const float* mlp_W  = (const float*)d_in[12];
    const float* mlp_b  = (const float*)d_in[13];
    float* out = (float*)d_out;

    const int M = in_sizes[0] / FIN;
    const int E = in_sizes[2];

    float *px, *phin, *pm, *pagg, *pgi, *pgh, *pbn, *pscale, *pshift;
    int *pei, *pflag;
    cudaGetSymbolAddress((void**)&px,     g_x);
    cudaGetSymbolAddress((void**)&phin,   g_hin);
    cudaGetSymbolAddress((void**)&pm,     g_m);
    cudaGetSymbolAddress((void**)&pagg,   g_agg);
    cudaGetSymbolAddress((void**)&pgi,    g_gi);
    cudaGetSymbolAddress((void**)&pgh,    g_gh);
    cudaGetSymbolAddress((void**)&pbn,    g_bnstats);
    cudaGetSymbolAddress((void**)&pscale, g_scale);
    cudaGetSymbolAddress((void**)&pshift, g_shift);
    cudaGetSymbolAddress((void**)&pei,    g_ei);
    cudaGetSymbolAddress((void**)&pflag,  g_flag);

    const dim3 blk(256);
    const int total = M * HH;
    const int mb = (M + 127) / 128;

    // 0. edge_index dtype probe + conversion to int32
    detect_idx_dtype<<<1, 1024>>>((const long long*)ei_raw, M, pflag);
    convert_idx<<<(2 * E + 255) / 256, 256>>>(ei_raw, 2 * E, pflag, pei);

    // 1. x = h @ emb_W + emb_b ; h_in = x
    sgemm128<<<dim3(1, mb), blk>>>(
        h, emb_W, emb_b, px, M, HH, FIN, 0, nullptr, nullptr, nullptr);
    cudaMemcpyAsync(phin, px, (size_t)total * sizeof(float), cudaMemcpyDeviceToDevice);

    // 2. L GatedGraphConv GRU steps
    for (int l = 0; l < LL; l++) {
        sgemm128<<<dim3(1, mb), blk>>>(
            px, conv_w + (size_t)l * HH * HH, nullptr, pm, M, HH, HH, 0,
            nullptr, nullptr, nullptr);
        zero_kernel<<<(total + 255) / 256, 256>>>(pagg, total);
        long long tth = (long long)E * 32;
        edge_scatter<<<(unsigned)((tth + 255) / 256), 256>>>(pei, ew, pm, pagg, E);
        sgemm128<<<dim3(3, mb), blk>>>(
            pagg, Wih, bih, pgi, M, 3 * HH, HH, 1, nullptr, nullptr, nullptr);
        sgemm128<<<dim3(3, mb), blk>>>(
            px, Whh, bhh, pgh, M, 3 * HH, HH, 1, nullptr, nullptr, nullptr);
        gru_update<<<(total + 255) / 256, 256>>>(pgi, pgh, px, total);
    }

    // 3. BatchNorm statistics -> per-feature scale/shift
    zero_kernel<<<1, 256>>>(pbn, 2 * HH);
    bn_stats<<<(M + 127) / 128, 128>>>(px, pbn, pbn + HH, M);
    bn_final<<<1, HH>>>(pbn, pbn + HH, gamma, beta, pscale, pshift, M);

    // 4. out = (BN(x) + h_in) @ mlp_W + mlp_b
    sgemm128<<<dim3(1, mb), blk>>>(
        px, mlp_W, mlp_b, out, M, CC, FIN, 0, phin, pscale, pshift);
}